// round 15
// baseline (speedup 1.0000x reference)
#include <cuda_runtime.h>
#include <cuda_fp16.h>
#include <cstdint>

// ---------------------------------------------------------------------------
// out[64,8192] = x[64,8192] @ dequant(B[1024,8192] int4-packed, s[64,8192])
// Split-K=2 HMMA fp16 GEMM, NO prep kernel: fp32 x loaded + converted to fp16
// in-loop (3-iter register prefetch), dequant B likewise. 256 thr/CTA,
// 2 CTAs/SM, 4-stage smem ring, barrier-only pipeline.
// ---------------------------------------------------------------------------

#define MDIM 64
#define KDIM 8192
#define NDIM 8192
#define NTILE 64
#define KTILE 64
#define KSPLIT 2
#define NIT (KDIM / KTILE / KSPLIT)  // 64 iters per k-half
#define ASTRIDE 144                  // smem row stride (64 fp16 + 16B pad)
#define NST 4
#define STG_BYTES (64 * ASTRIDE)             // 9216 per stage
#define SMEM_TOTAL (2 * NST * STG_BYTES)     // 73728 -> 2 CTAs/SM

// split-K partial for k-half 1
__device__ __align__(16) float g_part[MDIM * NDIM];

// ---------------------------- helpers ---------------------------------------
__device__ __forceinline__ uint32_t smem_u32(const void* p) {
    uint32_t a;
    asm("{ .reg .u64 t; cvta.to.shared.u64 t, %1; cvt.u32.u64 %0, t; }"
        : "=r"(a) : "l"(p));
    return a;
}

union HU { uint32_t u; __half2 h; };
__device__ __forceinline__ __half2 u2h(uint32_t u) { HU c; c.u = u; return c.h; }
__device__ __forceinline__ uint32_t h2u(__half2 h) { HU c; c.h = h; return c.u; }

// magic dequant: 8 int4 nibbles -> 8 fp16 * scale, k-order {0,4,1,5,2,6,3,7}
__device__ __forceinline__ uint4 dq8(uint32_t w, __half2 s2) {
    const __half2 c1032 = __half2half2(__ushort_as_half((unsigned short)0x6408)); // 1032.0
    uint4 o;
    o.x = h2u(__hmul2(__hsub2(u2h((w         & 0x000F000Fu) | 0x64006400u), c1032), s2));
    o.y = h2u(__hmul2(__hsub2(u2h(((w >> 4)  & 0x000F000Fu) | 0x64006400u), c1032), s2));
    o.z = h2u(__hmul2(__hsub2(u2h(((w >> 8)  & 0x000F000Fu) | 0x64006400u), c1032), s2));
    o.w = h2u(__hmul2(__hsub2(u2h(((w >> 12) & 0x000F000Fu) | 0x64006400u), c1032), s2));
    return o;
}

// pack 8 fp32 (two float4, natural k-order) into 8 fp16 in the dequant
// pair order (x0,x4),(x1,x5),(x2,x6),(x3,x7)
__device__ __forceinline__ uint4 cvt8(float4 a, float4 b) {
    uint4 o;
    o.x = h2u(__floats2half2_rn(a.x, b.x));
    o.y = h2u(__floats2half2_rn(a.y, b.y));
    o.z = h2u(__floats2half2_rn(a.z, b.z));
    o.w = h2u(__floats2half2_rn(a.w, b.w));
    return o;
}

#define LDSM4(r, addr)                                                          \
    asm volatile("ldmatrix.sync.aligned.m8n8.x4.shared.b16 {%0,%1,%2,%3}, [%4];"\
        : "=r"((r)[0]), "=r"((r)[1]), "=r"((r)[2]), "=r"((r)[3]) : "r"(addr))

#define MMA16816(c, a, bb0, bb1)                                                \
    asm volatile("mma.sync.aligned.m16n8k16.row.col.f32.f16.f16.f32 "           \
        "{%0,%1,%2,%3},{%4,%5,%6,%7},{%8,%9},{%0,%1,%2,%3};"                    \
        : "+f"((c)[0]), "+f"((c)[1]), "+f"((c)[2]), "+f"((c)[3])                \
        : "r"((a)[0]), "r"((a)[1]), "r"((a)[2]), "r"((a)[3]), "r"(bb0), "r"(bb1))

// ------------------------------- reduce: out += partial ----------------------
__global__ void reduce_kernel(float* __restrict__ out) {
    int i = blockIdx.x * 256 + threadIdx.x;
    float4 a = *(const float4*)(out + (size_t)i * 4);
    float4 b = *(const float4*)(g_part + (size_t)i * 4);
    a.x += b.x; a.y += b.y; a.z += b.z; a.w += b.w;
    *(float4*)(out + (size_t)i * 4) = a;
}

// ------------------------------- main kernel --------------------------------
__global__ void __launch_bounds__(256, 2)
machete_kernel(const float* __restrict__ gx, const int* __restrict__ gB,
               const float* __restrict__ gs, float* __restrict__ out) {
    extern __shared__ __align__(16) unsigned char dsm[];
    unsigned char* sA = dsm;                       // NST stages of A
    unsigned char* sW = dsm + NST * STG_BYTES;     // NST stages of W
    const uint32_t sAb0 = smem_u32(sA);
    const uint32_t sWb0 = smem_u32(sW);

    const int t = threadIdx.x;
    const int lane = t & 31;
    const int wid = t >> 5;
    const int n0 = blockIdx.x * NTILE;
    const int kp = blockIdx.y;                 // k-half 0 / 1

    // ---------------- load-phase mapping (all 256 threads) ----------------
    const int am = t >> 2, akq = t & 3;        // A: row, 16-element chunk
    const int wn = t & 63, kw2 = t >> 6;       // W: n-row, word-pair index
    const float* aptr = gx + (size_t)am * KDIM + (size_t)kp * (KDIM / 2) + akq * 16;
    const int*   bptr = gB + ((size_t)kp * 512 + 2 * kw2) * NDIM + n0 + wn;
    const float* sptr = gs + (size_t)kp * 32 * NDIM + n0 + wn;
    const uint32_t sAoff = (uint32_t)(am * ASTRIDE + akq * 32);
    const uint32_t sWoff = (uint32_t)(wn * ASTRIDE + kw2 * 32);

    float4   ra[2][4];       // A fp32 prefetch: 2 slots x 16 floats
    uint32_t rw[2][2];       // B prefetch slots
    float    rsv[2];

    auto ldgA = [&](int it) {
        const float4* ap = (const float4*)(aptr + (size_t)it * KTILE);
        const int sl = it & 1;
        ra[sl][0] = ap[0]; ra[sl][1] = ap[1]; ra[sl][2] = ap[2]; ra[sl][3] = ap[3];
    };
    auto stsA = [&](int it) {
        const int sl = it & 1;
        unsigned char* at = sA + (it & (NST - 1)) * STG_BYTES;
        *(uint4*)(at + sAoff)      = cvt8(ra[sl][0], ra[sl][1]);
        *(uint4*)(at + sAoff + 16) = cvt8(ra[sl][2], ra[sl][3]);
    };
    auto ldgB = [&](int it) {
        const int* bp = bptr + (size_t)it * 8 * NDIM;
        const int sl = it & 1;
        rw[sl][0] = bp[0];
        rw[sl][1] = bp[NDIM];
        rsv[sl] = sptr[(size_t)(it >> 1) * NDIM];
    };
    auto stsW = [&](int it) {
        const int sl = it & 1;
        const __half2 s2 = __half2half2(__float2half_rn(rsv[sl]));
        unsigned char* wt = sW + (it & (NST - 1)) * STG_BYTES;
        *(uint4*)(wt + sWoff)      = dq8(rw[sl][0], s2);
        *(uint4*)(wt + sWoff + 16) = dq8(rw[sl][1], s2);
    };

    // ---------------- compute-phase mapping ----------------
    // 4 output tiles of 32x32 (2m x 2n), 2 warps per tile split by k-step.
    const int tile  = wid >> 1;
    const int khalf = wid & 1;
    const int tm = (tile >> 1) * 32;
    const int tn = (tile & 1) * 32;
    const int mat = lane >> 3, mr = lane & 7;
    const uint32_t aRow = (uint32_t)((tm + (mat & 1) * 8 + mr) * ASTRIDE + (mat >> 1) * 16);
    const uint32_t bRow = (uint32_t)((tn + (mat >> 1) * 8 + mr) * ASTRIDE + (mat & 1) * 16);

    float acc[2][4][4];
    #pragma unroll
    for (int i = 0; i < 2; ++i)
        #pragma unroll
        for (int j = 0; j < 4; ++j)
            #pragma unroll
            for (int r = 0; r < 4; ++r) acc[i][j][r] = 0.f;

    auto compute = [&](int stg) {
        const uint32_t sAs = sAb0 + stg * STG_BYTES;
        const uint32_t sWs = sWb0 + stg * STG_BYTES;
        #pragma unroll
        for (int s = 0; s < 2; ++s) {
            const int ks = khalf + 2 * s;
            uint32_t a0[4], a1[4], b0[4], b1[4];
            LDSM4(a0, sAs + aRow + ks * 32);
            LDSM4(a1, sAs + aRow + 16 * ASTRIDE + ks * 32);
            LDSM4(b0, sWs + bRow + ks * 32);
            LDSM4(b1, sWs + bRow + 16 * ASTRIDE + ks * 32);
            MMA16816(acc[0][0], a0, b0[0], b0[1]);
            MMA16816(acc[0][1], a0, b0[2], b0[3]);
            MMA16816(acc[0][2], a0, b1[0], b1[1]);
            MMA16816(acc[0][3], a0, b1[2], b1[3]);
            MMA16816(acc[1][0], a1, b0[0], b0[1]);
            MMA16816(acc[1][1], a1, b0[2], b0[3]);
            MMA16816(acc[1][2], a1, b1[0], b1[1]);
            MMA16816(acc[1][3], a1, b1[2], b1[3]);
        }
    };

    // ---------------- prologue: stage 0 direct, slots for iters 1-2 ----------
    {
        const float4* ap = (const float4*)aptr;
        *(uint4*)(sA + sAoff)      = cvt8(ap[0], ap[1]);
        *(uint4*)(sA + sAoff + 16) = cvt8(ap[2], ap[3]);
        const __half2 s2 = __half2half2(__float2half_rn(sptr[0]));
        *(uint4*)(sW + sWoff)      = dq8(bptr[0], s2);
        *(uint4*)(sW + sWoff + 16) = dq8(bptr[NDIM], s2);
    }
    ldgA(1); ldgB(1);      // slot 1
    ldgA(2); ldgB(2);      // slot 0

    // ---------------- main pipeline (barrier-only) ----------------
    #pragma unroll 4
    for (int i = 0; i < NIT; ++i) {
        if (i + 1 < NIT) { stsA(i + 1); stsW(i + 1); }  // stage i+1
        if (i + 3 < NIT) { ldgA(i + 3); ldgB(i + 3); }  // 3-iter lookahead
        __syncthreads();                   // stage i visible to all
        compute(i & (NST - 1));
    }
    __syncthreads();                       // protect smem reuse below

    // ---------------- k-half reduction + writeout ----------------
    float* obase = (kp == 0) ? out : g_part;
    float* red = (float*)dsm;              // 4 tiles * 1024 floats = 16 KB
    if (khalf == 1) {
        float* dst = red + tile * 1024 + lane * 4;
        #pragma unroll
        for (int ms = 0; ms < 2; ++ms)
            #pragma unroll
            for (int ns = 0; ns < 4; ++ns) {
                float4 v = make_float4(acc[ms][ns][0], acc[ms][ns][1],
                                       acc[ms][ns][2], acc[ms][ns][3]);
                *(float4*)(dst + (ms * 4 + ns) * 128) = v;
            }
    }
    __syncthreads();
    if (khalf == 0) {
        const float* src = red + tile * 1024 + lane * 4;
        const int g = lane >> 2, cb = 2 * (lane & 3);
        #pragma unroll
        for (int ms = 0; ms < 2; ++ms)
            #pragma unroll
            for (int ns = 0; ns < 4; ++ns) {
                float4 v = *(const float4*)(src + (ms * 4 + ns) * 128);
                const int m = tm + ms * 16 + g;
                const int c = n0 + tn + ns * 8 + cb;
                float2 lo = make_float2(acc[ms][ns][0] + v.x, acc[ms][ns][1] + v.y);
                float2 hi = make_float2(acc[ms][ns][2] + v.z, acc[ms][ns][3] + v.w);
                *(float2*)(obase + (size_t)m * NDIM + c)       = lo;
                *(float2*)(obase + (size_t)(m + 8) * NDIM + c) = hi;
            }
    }
}

// ------------------------------- launch -------------------------------------
extern "C" void kernel_launch(void* const* d_in, const int* in_sizes, int n_in,
                              void* d_out, int out_size) {
    const float* x = (const float*)d_in[0];
    const int* B   = (const int*)d_in[1];
    const float* s = (const float*)d_in[2];
    float* out = (float*)d_out;

    cudaFuncSetAttribute(machete_kernel,
                         cudaFuncAttributeMaxDynamicSharedMemorySize, SMEM_TOTAL);

    dim3 grid(NDIM / NTILE, KSPLIT);
    machete_kernel<<<grid, 256, SMEM_TOTAL>>>(x, B, s, out);
    reduce_kernel<<<(MDIM * NDIM / 4 + 255) / 256, 256>>>(out);
}

// round 16
// speedup vs baseline: 1.5158x; 1.5158x over previous
#include <cuda_runtime.h>
#include <cuda_fp16.h>
#include <cstdint>

// ---------------------------------------------------------------------------
// out[64,8192] = x[64,8192] @ dequant(B[1024,8192] int4-packed, s[64,8192])
// Split-K=2 HMMA fp16 GEMM (R12 champion main loop, untouched) +
// ILP-optimized prep / reduce helper kernels.
// ---------------------------------------------------------------------------

#define MDIM 64
#define KDIM 8192
#define NDIM 8192
#define NTILE 64
#define KTILE 64
#define NIT (KDIM / KTILE / 2)   // 64 iters per k-half
#define ASTRIDE 144              // smem row stride (64 fp16 + 16B pad)
#define NST 4
#define STG_BYTES (64 * ASTRIDE)             // 9216 per stage
#define SMEM_TOTAL (2 * NST * STG_BYTES)     // 73728 -> 2 CTAs/SM

// fp16 x, pre-permuted: slot j of each 8-wide group holds x[8w + perm[j]],
// perm = {0,4,1,5,2,6,3,7} (the LOP3 magic-dequant output order).
__device__ __align__(16) __half g_xh[MDIM * KDIM];
// split-K partial for k-half 1
__device__ __align__(16) float g_part[MDIM * NDIM];

// ---------------------------- helpers ---------------------------------------
__device__ __forceinline__ uint32_t smem_u32(const void* p) {
    uint32_t a;
    asm("{ .reg .u64 t; cvta.to.shared.u64 t, %1; cvt.u32.u64 %0, t; }"
        : "=r"(a) : "l"(p));
    return a;
}

union HU { uint32_t u; __half2 h; };
__device__ __forceinline__ __half2 u2h(uint32_t u) { HU c; c.u = u; return c.h; }
__device__ __forceinline__ uint32_t h2u(__half2 h) { HU c; c.h = h; return c.u; }

// magic dequant: 8 int4 nibbles -> 8 fp16 * scale, k-order {0,4,1,5,2,6,3,7}
__device__ __forceinline__ uint4 dq8(uint32_t w, __half2 s2) {
    const __half2 c1032 = __half2half2(__ushort_as_half((unsigned short)0x6408)); // 1032.0
    uint4 o;
    o.x = h2u(__hmul2(__hsub2(u2h((w         & 0x000F000Fu) | 0x64006400u), c1032), s2));
    o.y = h2u(__hmul2(__hsub2(u2h(((w >> 4)  & 0x000F000Fu) | 0x64006400u), c1032), s2));
    o.z = h2u(__hmul2(__hsub2(u2h(((w >> 8)  & 0x000F000Fu) | 0x64006400u), c1032), s2));
    o.w = h2u(__hmul2(__hsub2(u2h(((w >> 12) & 0x000F000Fu) | 0x64006400u), c1032), s2));
    return o;
}

#define LDSM4(r, addr)                                                          \
    asm volatile("ldmatrix.sync.aligned.m8n8.x4.shared.b16 {%0,%1,%2,%3}, [%4];"\
        : "=r"((r)[0]), "=r"((r)[1]), "=r"((r)[2]), "=r"((r)[3]) : "r"(addr))

#define MMA16816(c, a, bb0, bb1)                                                \
    asm volatile("mma.sync.aligned.m16n8k16.row.col.f32.f16.f16.f32 "           \
        "{%0,%1,%2,%3},{%4,%5,%6,%7},{%8,%9},{%0,%1,%2,%3};"                    \
        : "+f"((c)[0]), "+f"((c)[1]), "+f"((c)[2]), "+f"((c)[3])                \
        : "r"((a)[0]), "r"((a)[1]), "r"((a)[2]), "r"((a)[3]), "r"(bb0), "r"(bb1))

#define CP_ASYNC16(dst, src) \
    asm volatile("cp.async.cg.shared.global [%0], [%1], 16;" :: "r"(dst), "l"(src))
#define CP_COMMIT() asm volatile("cp.async.commit_group;" ::: "memory")
#define CP_WAIT2()  asm volatile("cp.async.wait_group 2;" ::: "memory")

// ------------------------------- prep: x -> fp16 permuted (ILP=4) ------------
__global__ void prep_kernel(const float* __restrict__ x) {
    // 2 groups (16 floats) per thread; 4 independent LDG.128 up front.
    int g = (blockIdx.x * 256 + threadIdx.x) * 2;
    if (g < MDIM * KDIM / 8) {
        const float4* xp = (const float4*)(x + (size_t)g * 8);
        float4 a0 = xp[0], b0 = xp[1], a1 = xp[2], b1 = xp[3];
        __half h0[8], h1[8];
        h0[0] = __float2half_rn(a0.x); h0[1] = __float2half_rn(b0.x);
        h0[2] = __float2half_rn(a0.y); h0[3] = __float2half_rn(b0.y);
        h0[4] = __float2half_rn(a0.z); h0[5] = __float2half_rn(b0.z);
        h0[6] = __float2half_rn(a0.w); h0[7] = __float2half_rn(b0.w);
        h1[0] = __float2half_rn(a1.x); h1[1] = __float2half_rn(b1.x);
        h1[2] = __float2half_rn(a1.y); h1[3] = __float2half_rn(b1.y);
        h1[4] = __float2half_rn(a1.z); h1[5] = __float2half_rn(b1.z);
        h1[6] = __float2half_rn(a1.w); h1[7] = __float2half_rn(b1.w);
        uint4* op = (uint4*)(g_xh + (size_t)g * 8);
        op[0] = *(uint4*)h0;
        op[1] = *(uint4*)h1;
    }
}

// ------------------------------- reduce: out += partial (ILP=8) --------------
__global__ void reduce_kernel(float* __restrict__ out) {
    // 4 float4 per thread; 8 independent loads up front.
    int i = (blockIdx.x * 256 + threadIdx.x) * 4;
    float4* op = (float4*)(out + (size_t)i * 4);
    const float4* pp = (const float4*)(g_part + (size_t)i * 4);
    float4 a0 = op[0], a1 = op[1], a2 = op[2], a3 = op[3];
    float4 b0 = pp[0], b1 = pp[1], b2 = pp[2], b3 = pp[3];
    a0.x += b0.x; a0.y += b0.y; a0.z += b0.z; a0.w += b0.w;
    a1.x += b1.x; a1.y += b1.y; a1.z += b1.z; a1.w += b1.w;
    a2.x += b2.x; a2.y += b2.y; a2.z += b2.z; a2.w += b2.w;
    a3.x += b3.x; a3.y += b3.y; a3.z += b3.z; a3.w += b3.w;
    op[0] = a0; op[1] = a1; op[2] = a2; op[3] = a3;
}

// ------------------------------- main kernel (R12 champion, unchanged) -------
__global__ void __launch_bounds__(256, 2)
machete_kernel(const int* __restrict__ gB, const float* __restrict__ gs,
               float* __restrict__ out) {
    extern __shared__ __align__(16) unsigned char dsm[];
    unsigned char* sA = dsm;                       // NST stages of A
    unsigned char* sW = dsm + NST * STG_BYTES;     // NST stages of W
    const uint32_t sAb0 = smem_u32(sA);
    const uint32_t sWb0 = smem_u32(sW);

    const int t = threadIdx.x;
    const int lane = t & 31;
    const int wid = t >> 5;
    const int n0 = blockIdx.x * NTILE;
    const int kp = blockIdx.y;                 // k-half 0 / 1

    // ---------------- load-phase mapping (all 256 threads) ----------------
    const int am = t >> 2, akq = t & 3;        // A: row, 32B chunk
    const int wn = t & 63, kw2 = t >> 6;       // W: n-row, word-pair index
    const __half* aptr = g_xh + (size_t)am * KDIM + (size_t)kp * (KDIM / 2) + akq * 16;
    const int*    bptr = gB + ((size_t)kp * 512 + 2 * kw2) * NDIM + n0 + wn;
    const float*  sptr = gs + (size_t)kp * 32 * NDIM + n0 + wn;
    const uint32_t sAoff = (uint32_t)(am * ASTRIDE + akq * 32);
    const uint32_t sWoff = (uint32_t)(wn * ASTRIDE + kw2 * 32);

    uint32_t rw[2][2];       // B prefetch slots (iter parity)
    float    rsv[2];

    auto ldgB = [&](int it) {
        const int* bp = bptr + (size_t)it * 8 * NDIM;
        const int sl = it & 1;
        rw[sl][0] = bp[0];
        rw[sl][1] = bp[NDIM];
        rsv[sl] = sptr[(size_t)(it >> 1) * NDIM];
    };
    auto stsW = [&](int it) {
        const int sl = it & 1;
        const __half2 s2 = __half2half2(__float2half_rn(rsv[sl]));
        unsigned char* wt = sW + (it & (NST - 1)) * STG_BYTES;
        *(uint4*)(wt + sWoff)      = dq8(rw[sl][0], s2);
        *(uint4*)(wt + sWoff + 16) = dq8(rw[sl][1], s2);
    };
    auto cpA = [&](int it) {
        const uint32_t dst = sAb0 + (it & (NST - 1)) * STG_BYTES + sAoff;
        const __half* src = aptr + it * KTILE;
        CP_ASYNC16(dst, src);
        CP_ASYNC16(dst + 16, src + 8);
    };

    // ---------------- compute-phase mapping ----------------
    // 4 output tiles of 32x32 (2m x 2n), 2 warps per tile split by k-step.
    const int tile  = wid >> 1;
    const int khalf = wid & 1;
    const int tm = (tile >> 1) * 32;
    const int tn = (tile & 1) * 32;
    const int mat = lane >> 3, mr = lane & 7;
    const uint32_t aRow = (uint32_t)((tm + (mat & 1) * 8 + mr) * ASTRIDE + (mat >> 1) * 16);
    const uint32_t bRow = (uint32_t)((tn + (mat >> 1) * 8 + mr) * ASTRIDE + (mat & 1) * 16);

    float acc[2][4][4];
    #pragma unroll
    for (int i = 0; i < 2; ++i)
        #pragma unroll
        for (int j = 0; j < 4; ++j)
            #pragma unroll
            for (int r = 0; r < 4; ++r) acc[i][j][r] = 0.f;

    auto compute = [&](int stg) {
        const uint32_t sAs = sAb0 + stg * STG_BYTES;
        const uint32_t sWs = sWb0 + stg * STG_BYTES;
        #pragma unroll
        for (int s = 0; s < 2; ++s) {
            const int ks = khalf + 2 * s;
            uint32_t a0[4], a1[4], b0[4], b1[4];
            LDSM4(a0, sAs + aRow + ks * 32);
            LDSM4(a1, sAs + aRow + 16 * ASTRIDE + ks * 32);
            LDSM4(b0, sWs + bRow + ks * 32);
            LDSM4(b1, sWs + bRow + 16 * ASTRIDE + ks * 32);
            MMA16816(acc[0][0], a0, b0[0], b0[1]);
            MMA16816(acc[0][1], a0, b0[2], b0[3]);
            MMA16816(acc[0][2], a0, b1[0], b1[1]);
            MMA16816(acc[0][3], a0, b1[2], b1[3]);
            MMA16816(acc[1][0], a1, b0[0], b0[1]);
            MMA16816(acc[1][1], a1, b0[2], b0[3]);
            MMA16816(acc[1][2], a1, b1[0], b1[1]);
            MMA16816(acc[1][3], a1, b1[2], b1[3]);
        }
    };

    // ---------------- prologue ----------------
    {   // iter 0 W: load directly and store to stage 0
        const __half2 s2 = __half2half2(__float2half_rn(sptr[0]));
        *(uint4*)(sW + sWoff)      = dq8(bptr[0], s2);
        *(uint4*)(sW + sWoff + 16) = dq8(bptr[NDIM], s2);
    }
    ldgB(1);            // slot 1
    ldgB(2);            // slot 0
    cpA(0); CP_COMMIT();
    cpA(1); CP_COMMIT();

    // ---------------- main pipeline ----------------
    #pragma unroll 4
    for (int i = 0; i < NIT; ++i) {
        if (i + 1 < NIT) stsW(i + 1);      // dequant+store W for next iter
        if (i + 3 < NIT) ldgB(i + 3);      // B prefetch, 3 ahead
        if (i + 2 < NIT) cpA(i + 2);       // A prefetch, 2 ahead
        CP_COMMIT();
        CP_WAIT2();                        // A stage i arrived (this thread)
        __syncthreads();                   // stage i visible to all
        compute(i & (NST - 1));
    }
    __syncthreads();                       // protect smem reuse below

    // ---------------- k-half reduction + writeout ----------------
    float* obase = (kp == 0) ? out : g_part;
    float* red = (float*)dsm;              // 4 tiles * 1024 floats = 16 KB
    if (khalf == 1) {
        float* dst = red + tile * 1024 + lane * 4;
        #pragma unroll
        for (int ms = 0; ms < 2; ++ms)
            #pragma unroll
            for (int ns = 0; ns < 4; ++ns) {
                float4 v = make_float4(acc[ms][ns][0], acc[ms][ns][1],
                                       acc[ms][ns][2], acc[ms][ns][3]);
                *(float4*)(dst + (ms * 4 + ns) * 128) = v;
            }
    }
    __syncthreads();
    if (khalf == 0) {
        const float* src = red + tile * 1024 + lane * 4;
        const int g = lane >> 2, cb = 2 * (lane & 3);
        #pragma unroll
        for (int ms = 0; ms < 2; ++ms)
            #pragma unroll
            for (int ns = 0; ns < 4; ++ns) {
                float4 v = *(const float4*)(src + (ms * 4 + ns) * 128);
                const int m = tm + ms * 16 + g;
                const int c = n0 + tn + ns * 8 + cb;
                float2 lo = make_float2(acc[ms][ns][0] + v.x, acc[ms][ns][1] + v.y);
                float2 hi = make_float2(acc[ms][ns][2] + v.z, acc[ms][ns][3] + v.w);
                *(float2*)(obase + (size_t)m * NDIM + c)       = lo;
                *(float2*)(obase + (size_t)(m + 8) * NDIM + c) = hi;
            }
    }
}

// ------------------------------- launch -------------------------------------
extern "C" void kernel_launch(void* const* d_in, const int* in_sizes, int n_in,
                              void* d_out, int out_size) {
    const float* x = (const float*)d_in[0];
    const int* B   = (const int*)d_in[1];
    const float* s = (const float*)d_in[2];
    float* out = (float*)d_out;

    cudaFuncSetAttribute(machete_kernel,
                         cudaFuncAttributeMaxDynamicSharedMemorySize, SMEM_TOTAL);

    prep_kernel<<<(MDIM * KDIM / 16 + 255) / 256, 256>>>(x);
    dim3 grid(NDIM / NTILE, 2);
    machete_kernel<<<grid, 256, SMEM_TOTAL>>>(B, s, out);
    reduce_kernel<<<(MDIM * NDIM / 16 + 255) / 256, 256>>>(out);
}